// round 1
// baseline (speedup 1.0000x reference)
#include <cuda_runtime.h>
#include <math.h>

// Problem constants
#define Vn 10000
#define Hn 512
#define On 512
#define Bn 256
#define Sn 256
#define N1 1536   // 2H (gates x-part) + H (cand x-part)

// ---------------- scratch (static device globals; no runtime alloc) --------
__device__ float g_EmbW[Vn * N1];                 // [V, 1536] precomputed emb @ [WgX|WhX]^T
__device__ float g_WxT [Hn * N1];                 // [k][n]  n<1024: Wg[n,k], else Wh[n-1024,k]
__device__ float g_WgHt[Hn * 1024];               // [k][j] = Wg[j, 512+k]
__device__ float g_WhHt[Hn * Hn];                 // [k][j] = Wh[j, 512+k]
__device__ float g_WoT [Hn * On];                 // [k][o] = Wo[o, k]
__device__ float g_h   [Bn * Hn];                 // hidden state
__device__ float g_z   [Bn * Hn];                 // update gate
__device__ float g_rh  [Bn * Hn];                 // r * h
__device__ float g_Hs  [(size_t)Bn * Sn * Hn];    // all hidden states [b, t, j]

// ---------------- weight packing (transposes for k-major GEMM B) -----------
__global__ void pack_weights(const float* __restrict__ Wg,
                             const float* __restrict__ Wh,
                             const float* __restrict__ Wo) {
    int idx = blockIdx.x * blockDim.x + threadIdx.x;
    const int s1 = Hn * N1;       // 786432
    const int s2 = Hn * 1024;     // 524288
    const int s3 = Hn * Hn;       // 262144
    const int s4 = Hn * On;       // 262144
    if (idx < s1) {
        int k = idx / N1, n = idx % N1;
        g_WxT[idx] = (n < 1024) ? Wg[n * 1024 + k] : Wh[(n - 1024) * 1024 + k];
    } else if (idx < s1 + s2) {
        int r = idx - s1; int k = r / 1024, j = r % 1024;
        g_WgHt[r] = Wg[j * 1024 + 512 + k];
    } else if (idx < s1 + s2 + s3) {
        int r = idx - s1 - s2; int k = r / 512, j = r % 512;
        g_WhHt[r] = Wh[j * 1024 + 512 + k];
    } else if (idx < s1 + s2 + s3 + s4) {
        int r = idx - s1 - s2 - s3; int k = r / 512, o = r % 512;
        g_WoT[r] = Wo[o * 512 + k];
    }
}

// ---------------- generic fp32 GEMM: C[M,N] = A[M,K] @ Bt[K,N] (+bias) -----
// 64x64 block tile, Kc=16, 256 threads, 4x4 micro-tile.
__global__ void gemm64(const float* __restrict__ A, const float* __restrict__ Bt,
                       float* __restrict__ C, const float* __restrict__ bias,
                       int M, int N, int K) {
    __shared__ float As[16][65];   // [kk][m], padded
    __shared__ float Bs[16][64];   // [kk][n]
    int tid = threadIdx.x;
    int tx = tid & 15, ty = tid >> 4;
    int nBase = blockIdx.x * 64;
    int mBase = blockIdx.y * 64;
    float acc[4][4] = {};
    for (int k0 = 0; k0 < K; k0 += 16) {
        #pragma unroll
        for (int l = 0; l < 4; l++) {
            int idx = tid + l * 256;
            int kk = idx & 15, m = idx >> 4;
            int gm = mBase + m;
            As[kk][m] = (gm < M) ? A[(size_t)gm * K + k0 + kk] : 0.f;
        }
        #pragma unroll
        for (int l = 0; l < 4; l++) {
            int idx = tid + l * 256;
            int nn = idx & 63, kk = idx >> 6;
            Bs[kk][nn] = Bt[(size_t)(k0 + kk) * N + nBase + nn];
        }
        __syncthreads();
        #pragma unroll
        for (int kk = 0; kk < 16; kk++) {
            float a[4], b[4];
            #pragma unroll
            for (int i = 0; i < 4; i++) a[i] = As[kk][ty * 4 + i];
            #pragma unroll
            for (int j = 0; j < 4; j++) b[j] = Bs[kk][tx * 4 + j];
            #pragma unroll
            for (int i = 0; i < 4; i++)
                #pragma unroll
                for (int j = 0; j < 4; j++)
                    acc[i][j] = fmaf(a[i], b[j], acc[i][j]);
        }
        __syncthreads();
    }
    #pragma unroll
    for (int i = 0; i < 4; i++) {
        int gm = mBase + ty * 4 + i;
        if (gm >= M) continue;
        #pragma unroll
        for (int j = 0; j < 4; j++) {
            int gn = nBase + tx * 4 + j;
            float v = acc[i][j];
            if (bias) v += bias[gn];
            C[(size_t)gm * N + gn] = v;
        }
    }
}

// ---------------- recurrence phase 1: gates ---------------------------------
// gh[b,j] = h[b,:] @ WgHt[:,j]; g = gh + EmbW[x[b,t], j] + bg[j]; s=sigmoid(g)
// j<512 -> z, j>=512 -> rh = s * h
// btile=32, jtile=64, 256 threads, 2x4 micro; grid (16, 8)
__global__ void gru_phase1(const int* __restrict__ x, const float* __restrict__ bg, int t) {
    __shared__ float As[16][33];
    __shared__ float Bs[16][64];
    int tid = threadIdx.x;
    int tx = tid & 15, ty = tid >> 4;          // ty in [0,16)
    int jBase = blockIdx.x * 64;
    int bBase = blockIdx.y * 32;
    float acc[2][4] = {};
    for (int k0 = 0; k0 < 512; k0 += 16) {
        #pragma unroll
        for (int l = 0; l < 2; l++) {
            int idx = tid + l * 256;
            int kk = idx & 15, m = idx >> 4;
            As[kk][m] = g_h[(bBase + m) * 512 + k0 + kk];
        }
        #pragma unroll
        for (int l = 0; l < 4; l++) {
            int idx = tid + l * 256;
            int nn = idx & 63, kk = idx >> 6;
            Bs[kk][nn] = g_WgHt[(k0 + kk) * 1024 + jBase + nn];
        }
        __syncthreads();
        #pragma unroll
        for (int kk = 0; kk < 16; kk++) {
            float a0 = As[kk][ty * 2];
            float a1 = As[kk][ty * 2 + 1];
            float b[4];
            #pragma unroll
            for (int j = 0; j < 4; j++) b[j] = Bs[kk][tx * 4 + j];
            #pragma unroll
            for (int j = 0; j < 4; j++) {
                acc[0][j] = fmaf(a0, b[j], acc[0][j]);
                acc[1][j] = fmaf(a1, b[j], acc[1][j]);
            }
        }
        __syncthreads();
    }
    #pragma unroll
    for (int i = 0; i < 2; i++) {
        int b = bBase + ty * 2 + i;
        int tok = x[b * Sn + t];
        const float* ew = g_EmbW + (size_t)tok * N1;
        #pragma unroll
        for (int j = 0; j < 4; j++) {
            int jj = jBase + tx * 4 + j;
            float g = acc[i][j] + ew[jj] + bg[jj];
            float s = 1.f / (1.f + expf(-g));
            if (jj < 512) {
                g_z[b * 512 + jj] = s;
            } else {
                int c = jj - 512;
                g_rh[b * 512 + c] = s * g_h[b * 512 + c];
            }
        }
    }
}

// ---------------- recurrence phase 2: candidate + state update --------------
// ch[b,j] = rh[b,:] @ WhHt[:,j]; cand = tanh(ch + EmbW[tok,1024+j] + bh[j])
// h_new = (1-z)h + z*cand; store to g_h and g_Hs[b,t,:]
// btile=16, jtile=64, 128 threads, 2x4 micro; grid (8, 16)
__global__ void gru_phase2(const int* __restrict__ x, const float* __restrict__ bh, int t) {
    __shared__ float As[16][17];
    __shared__ float Bs[16][64];
    int tid = threadIdx.x;                     // 128 threads
    int tx = tid & 15, ty = tid >> 4;          // ty in [0,8)
    int jBase = blockIdx.x * 64;
    int bBase = blockIdx.y * 16;
    float acc[2][4] = {};
    for (int k0 = 0; k0 < 512; k0 += 16) {
        #pragma unroll
        for (int l = 0; l < 2; l++) {
            int idx = tid + l * 128;
            int kk = idx & 15, m = idx >> 4;
            As[kk][m] = g_rh[(bBase + m) * 512 + k0 + kk];
        }
        #pragma unroll
        for (int l = 0; l < 8; l++) {
            int idx = tid + l * 128;
            int nn = idx & 63, kk = idx >> 6;
            Bs[kk][nn] = g_WhHt[(k0 + kk) * 512 + jBase + nn];
        }
        __syncthreads();
        #pragma unroll
        for (int kk = 0; kk < 16; kk++) {
            float a0 = As[kk][ty * 2];
            float a1 = As[kk][ty * 2 + 1];
            float b[4];
            #pragma unroll
            for (int j = 0; j < 4; j++) b[j] = Bs[kk][tx * 4 + j];
            #pragma unroll
            for (int j = 0; j < 4; j++) {
                acc[0][j] = fmaf(a0, b[j], acc[0][j]);
                acc[1][j] = fmaf(a1, b[j], acc[1][j]);
            }
        }
        __syncthreads();
    }
    #pragma unroll
    for (int i = 0; i < 2; i++) {
        int b = bBase + ty * 2 + i;
        int tok = x[b * Sn + t];
        #pragma unroll
        for (int j = 0; j < 4; j++) {
            int jj = jBase + tx * 4 + j;
            float c = tanhf(acc[i][j] + g_EmbW[(size_t)tok * N1 + 1024 + jj] + bh[jj]);
            float z = g_z[b * 512 + jj];
            float hp = g_h[b * 512 + jj];
            float hn = (1.f - z) * hp + z * c;
            g_h[b * 512 + jj] = hn;
            g_Hs[((size_t)b * Sn + t) * 512 + jj] = hn;
        }
    }
}

// ---------------- tiny helpers ----------------------------------------------
__global__ void zero_h() {
    int i = blockIdx.x * blockDim.x + threadIdx.x;
    if (i < Bn * Hn) g_h[i] = 0.f;
}
__global__ void copy_h(float* __restrict__ out) {
    int i = blockIdx.x * blockDim.x + threadIdx.x;
    if (i < Bn * Hn) out[i] = g_h[i];
}

// ---------------- entry ------------------------------------------------------
extern "C" void kernel_launch(void* const* d_in, const int* in_sizes, int n_in,
                              void* d_out, int out_size) {
    const int*   x   = (const int*)  d_in[0];
    const float* emb = (const float*)d_in[1];
    const float* Wg  = (const float*)d_in[2];
    const float* bg  = (const float*)d_in[3];
    const float* Wh  = (const float*)d_in[4];
    const float* bh  = (const float*)d_in[5];
    const float* Wo  = (const float*)d_in[6];
    const float* bo  = (const float*)d_in[7];
    float* out = (float*)d_out;

    float *pEmbW, *pWxT, *pWoT, *pHs;
    cudaGetSymbolAddress((void**)&pEmbW, g_EmbW);
    cudaGetSymbolAddress((void**)&pWxT,  g_WxT);
    cudaGetSymbolAddress((void**)&pWoT,  g_WoT);
    cudaGetSymbolAddress((void**)&pHs,   g_Hs);

    // 1. Pack/transpose weights
    pack_weights<<<7168, 256>>>(Wg, Wh, Wo);

    // 2. Precompute per-vocab input projections: EmbW[V,1536] = emb @ WxT
    gemm64<<<dim3(N1 / 64, (Vn + 63) / 64), 256>>>(emb, pWxT, pEmbW, nullptr, Vn, N1, Hn);

    // 3. Recurrence
    zero_h<<<(Bn * Hn + 255) / 256, 256>>>();
    for (int t = 0; t < Sn; t++) {
        gru_phase1<<<dim3(16, 8), 256>>>(x, bg, t);
        gru_phase2<<<dim3(8, 16), 128>>>(x, bh, t);
    }

    // 4. Output projection: ys[b,t,o] = Hs[b,t,:] @ WoT + bo
    gemm64<<<dim3(On / 64, (Bn * Sn) / 64), 256>>>(pHs, pWoT, out + Bn * Hn, bo,
                                                   Bn * Sn, On, Hn);

    // 5. h_final at front of output
    copy_h<<<(Bn * Hn + 255) / 256, 256>>>(out);
}

// round 2
// speedup vs baseline: 1.4908x; 1.4908x over previous
#include <cuda_runtime.h>
#include <math.h>

// Problem constants
#define Vn 10000
#define Hn 512
#define On 512
#define Bn 256
#define Sn 256
#define N1 1536   // 2H (gates x-part) + H (cand x-part)

// ---------------- scratch (static device globals; no runtime alloc) --------
__device__ float g_EmbW[Vn * N1];                 // [V, 1536] precomputed emb @ [WgX|WhX]^T
__device__ float g_WxT [Hn * N1];                 // [k][n]  n<1024: Wg[n,k], else Wh[n-1024,k]
__device__ float g_WgHt[Hn * 1024];               // [k][j] = Wg[j, 512+k]
__device__ float g_WhHt[Hn * Hn];                 // [k][j] = Wh[j, 512+k]
__device__ float g_WoT [Hn * On];                 // [k][o] = Wo[o, k]
__device__ float g_h   [Bn * Hn];                 // hidden state
__device__ float g_z   [Bn * Hn];                 // update gate
__device__ float g_rh  [Bn * Hn];                 // r * h
__device__ float g_Hs  [(size_t)Bn * Sn * Hn];    // all hidden states [b, t, j]

// ---------------- weight packing (transposes for k-major GEMM B) -----------
__global__ void pack_weights(const float* __restrict__ Wg,
                             const float* __restrict__ Wh,
                             const float* __restrict__ Wo) {
    int idx = blockIdx.x * blockDim.x + threadIdx.x;
    const int s1 = Hn * N1;       // 786432
    const int s2 = Hn * 1024;     // 524288
    const int s3 = Hn * Hn;       // 262144
    const int s4 = Hn * On;       // 262144
    if (idx < s1) {
        int k = idx / N1, n = idx % N1;
        g_WxT[idx] = (n < 1024) ? Wg[n * 1024 + k] : Wh[(n - 1024) * 1024 + k];
    } else if (idx < s1 + s2) {
        int r = idx - s1; int k = r / 1024, j = r % 1024;
        g_WgHt[r] = Wg[j * 1024 + 512 + k];
    } else if (idx < s1 + s2 + s3) {
        int r = idx - s1 - s2; int k = r / 512, j = r % 512;
        g_WhHt[r] = Wh[j * 1024 + 512 + k];
    } else if (idx < s1 + s2 + s3 + s4) {
        int r = idx - s1 - s2 - s3; int k = r / 512, o = r % 512;
        g_WoT[r] = Wo[o * 512 + k];
    }
}

// ---------------- generic fp32 GEMM: C[M,N] = A[M,K] @ Bt[K,N] (+bias) -----
// 64x64 block tile, Kc=16, 256 threads, 4x4 micro-tile.
__global__ void gemm64(const float* __restrict__ A, const float* __restrict__ Bt,
                       float* __restrict__ C, const float* __restrict__ bias,
                       int M, int N, int K) {
    __shared__ float As[16][65];   // [kk][m], padded
    __shared__ float Bs[16][64];   // [kk][n]
    int tid = threadIdx.x;
    int tx = tid & 15, ty = tid >> 4;
    int nBase = blockIdx.x * 64;
    int mBase = blockIdx.y * 64;
    float acc[4][4] = {};
    for (int k0 = 0; k0 < K; k0 += 16) {
        #pragma unroll
        for (int l = 0; l < 4; l++) {
            int idx = tid + l * 256;
            int kk = idx & 15, m = idx >> 4;
            int gm = mBase + m;
            As[kk][m] = (gm < M) ? A[(size_t)gm * K + k0 + kk] : 0.f;
        }
        #pragma unroll
        for (int l = 0; l < 4; l++) {
            int idx = tid + l * 256;
            int nn = idx & 63, kk = idx >> 6;
            Bs[kk][nn] = Bt[(size_t)(k0 + kk) * N + nBase + nn];
        }
        __syncthreads();
        #pragma unroll
        for (int kk = 0; kk < 16; kk++) {
            float a[4], b[4];
            #pragma unroll
            for (int i = 0; i < 4; i++) a[i] = As[kk][ty * 4 + i];
            #pragma unroll
            for (int j = 0; j < 4; j++) b[j] = Bs[kk][tx * 4 + j];
            #pragma unroll
            for (int i = 0; i < 4; i++)
                #pragma unroll
                for (int j = 0; j < 4; j++)
                    acc[i][j] = fmaf(a[i], b[j], acc[i][j]);
        }
        __syncthreads();
    }
    #pragma unroll
    for (int i = 0; i < 4; i++) {
        int gm = mBase + ty * 4 + i;
        if (gm >= M) continue;
        #pragma unroll
        for (int j = 0; j < 4; j++) {
            int gn = nBase + tx * 4 + j;
            float v = acc[i][j];
            if (bias) v += bias[gn];
            C[(size_t)gm * N + gn] = v;
        }
    }
}

// ---------------- recurrence phase 1: gates ---------------------------------
// gh[b,j] = h[b,:] @ WgHt[:,j]; g = gh + EmbW[x[b,t], j] + bg[j]; s=sigmoid(g)
// j<512 -> z, j>=512 -> rh = s * h
// btile=32, jtile=64, 256 threads, 2x4 micro; grid (16, 8)
__global__ void gru_phase1(const int* __restrict__ x, const float* __restrict__ bg, int t) {
    __shared__ float As[16][33];
    __shared__ float Bs[16][64];
    int tid = threadIdx.x;
    int tx = tid & 15, ty = tid >> 4;          // ty in [0,16)
    int jBase = blockIdx.x * 64;
    int bBase = blockIdx.y * 32;
    float acc[2][4] = {};
    for (int k0 = 0; k0 < 512; k0 += 16) {
        #pragma unroll
        for (int l = 0; l < 2; l++) {
            int idx = tid + l * 256;
            int kk = idx & 15, m = idx >> 4;
            As[kk][m] = g_h[(bBase + m) * 512 + k0 + kk];
        }
        #pragma unroll
        for (int l = 0; l < 4; l++) {
            int idx = tid + l * 256;
            int nn = idx & 63, kk = idx >> 6;
            Bs[kk][nn] = g_WgHt[(k0 + kk) * 1024 + jBase + nn];
        }
        __syncthreads();
        #pragma unroll
        for (int kk = 0; kk < 16; kk++) {
            float a0 = As[kk][ty * 2];
            float a1 = As[kk][ty * 2 + 1];
            float b[4];
            #pragma unroll
            for (int j = 0; j < 4; j++) b[j] = Bs[kk][tx * 4 + j];
            #pragma unroll
            for (int j = 0; j < 4; j++) {
                acc[0][j] = fmaf(a0, b[j], acc[0][j]);
                acc[1][j] = fmaf(a1, b[j], acc[1][j]);
            }
        }
        __syncthreads();
    }
    #pragma unroll
    for (int i = 0; i < 2; i++) {
        int b = bBase + ty * 2 + i;
        int tok = x[b * Sn + t];
        const float* ew = g_EmbW + (size_t)tok * N1;
        #pragma unroll
        for (int j = 0; j < 4; j++) {
            int jj = jBase + tx * 4 + j;
            float g = acc[i][j] + ew[jj] + bg[jj];
            float s = 1.f / (1.f + expf(-g));
            if (jj < 512) {
                g_z[b * 512 + jj] = s;
            } else {
                int c = jj - 512;
                g_rh[b * 512 + c] = s * g_h[b * 512 + c];
            }
        }
    }
}

// ---------------- recurrence phase 2: candidate + state update --------------
// ch[b,j] = rh[b,:] @ WhHt[:,j]; cand = tanh(ch + EmbW[tok,1024+j] + bh[j])
// h_new = (1-z)h + z*cand; store to g_h and g_Hs[b,t,:]
// btile=16, jtile=64, 128 threads, 2x4 micro; grid (8, 16)
__global__ void gru_phase2(const int* __restrict__ x, const float* __restrict__ bh, int t) {
    __shared__ float As[16][17];
    __shared__ float Bs[16][64];
    int tid = threadIdx.x;                     // 128 threads
    int tx = tid & 15, ty = tid >> 4;          // ty in [0,8)
    int jBase = blockIdx.x * 64;
    int bBase = blockIdx.y * 16;
    float acc[2][4] = {};
    for (int k0 = 0; k0 < 512; k0 += 16) {
        #pragma unroll
        for (int l = 0; l < 2; l++) {
            int idx = tid + l * 128;
            int kk = idx & 15, m = idx >> 4;
            As[kk][m] = g_rh[(bBase + m) * 512 + k0 + kk];
        }
        #pragma unroll
        for (int l = 0; l < 8; l++) {
            int idx = tid + l * 128;
            int nn = idx & 63, kk = idx >> 6;
            Bs[kk][nn] = g_WhHt[(k0 + kk) * 512 + jBase + nn];
        }
        __syncthreads();
        #pragma unroll
        for (int kk = 0; kk < 16; kk++) {
            float a0 = As[kk][ty * 2];
            float a1 = As[kk][ty * 2 + 1];
            float b[4];
            #pragma unroll
            for (int j = 0; j < 4; j++) b[j] = Bs[kk][tx * 4 + j];
            #pragma unroll
            for (int j = 0; j < 4; j++) {
                acc[0][j] = fmaf(a0, b[j], acc[0][j]);
                acc[1][j] = fmaf(a1, b[j], acc[1][j]);
            }
        }
        __syncthreads();
    }
    #pragma unroll
    for (int i = 0; i < 2; i++) {
        int b = bBase + ty * 2 + i;
        int tok = x[b * Sn + t];
        #pragma unroll
        for (int j = 0; j < 4; j++) {
            int jj = jBase + tx * 4 + j;
            float c = tanhf(acc[i][j] + g_EmbW[(size_t)tok * N1 + 1024 + jj] + bh[jj]);
            float z = g_z[b * 512 + jj];
            float hp = g_h[b * 512 + jj];
            float hn = (1.f - z) * hp + z * c;
            g_h[b * 512 + jj] = hn;
            g_Hs[((size_t)b * Sn + t) * 512 + jj] = hn;
        }
    }
}

// ---------------- tiny helpers ----------------------------------------------
__global__ void zero_h() {
    int i = blockIdx.x * blockDim.x + threadIdx.x;
    if (i < Bn * Hn) g_h[i] = 0.f;
}
__global__ void copy_h(float* __restrict__ out) {
    int i = blockIdx.x * blockDim.x + threadIdx.x;
    if (i < Bn * Hn) out[i] = g_h[i];
}

// ---------------- entry ------------------------------------------------------
extern "C" void kernel_launch(void* const* d_in, const int* in_sizes, int n_in,
                              void* d_out, int out_size) {
    const int*   x   = (const int*)  d_in[0];
    const float* emb = (const float*)d_in[1];
    const float* Wg  = (const float*)d_in[2];
    const float* bg  = (const float*)d_in[3];
    const float* Wh  = (const float*)d_in[4];
    const float* bh  = (const float*)d_in[5];
    const float* Wo  = (const float*)d_in[6];
    const float* bo  = (const float*)d_in[7];
    float* out = (float*)d_out;

    float *pEmbW, *pWxT, *pWoT, *pHs;
    cudaGetSymbolAddress((void**)&pEmbW, g_EmbW);
    cudaGetSymbolAddress((void**)&pWxT,  g_WxT);
    cudaGetSymbolAddress((void**)&pWoT,  g_WoT);
    cudaGetSymbolAddress((void**)&pHs,   g_Hs);

    // 1. Pack/transpose weights
    pack_weights<<<7168, 256>>>(Wg, Wh, Wo);

    // 2. Precompute per-vocab input projections: EmbW[V,1536] = emb @ WxT
    gemm64<<<dim3(N1 / 64, (Vn + 63) / 64), 256>>>(emb, pWxT, pEmbW, nullptr, Vn, N1, Hn);

    // 3. Recurrence
    zero_h<<<(Bn * Hn + 255) / 256, 256>>>();
    for (int t = 0; t < Sn; t++) {
        gru_phase1<<<dim3(16, 8), 256>>>(x, bg, t);
        gru_phase2<<<dim3(8, 16), 128>>>(x, bh, t);
    }

    // 4. Output projection: ys[b,t,o] = Hs[b,t,:] @ WoT + bo
    gemm64<<<dim3(On / 64, (Bn * Sn) / 64), 256>>>(pHs, pWoT, out + Bn * Hn, bo,
                                                   Bn * Sn, On, Hn);

    // 5. h_final at front of output
    copy_h<<<(Bn * Hn + 255) / 256, 256>>>(out);
}

// round 3
// speedup vs baseline: 2.3839x; 1.5991x over previous
#include <cuda_runtime.h>
#include <math.h>
#include <stdint.h>

#define Vn 10000
#define Hn 512
#define On 512
#define Bn 256
#define Sn 256
#define N1 1536

#define NJ 16
#define NG 8
#define RB 32
#define PAD_WG 68
#define PAD_WH 36
#define PAD_ST 132
#define SMEM_BYTES ((512*PAD_WG + 512*PAD_WH + 32*PAD_ST) * 4)

// ---------------- scratch ----------------------------------------------------
__device__ float g_EmbW[(size_t)Vn * N1];
__device__ float g_WxT [Hn * N1];
__device__ float g_WgHt[Hn * 1024];
__device__ float g_WhHt[Hn * Hn];
__device__ float g_WoT [Hn * On];
__device__ float g_h   [Bn * Hn];
__device__ float g_z   [Bn * Hn];
__device__ float g_rh  [Bn * Hn];
__device__ float g_Hs  [(size_t)Bn * Sn * Hn];
__device__ int   g_ctr [NG];

// ---------------- helpers ----------------------------------------------------
__device__ __forceinline__ float f2tff(float f) {
    uint32_t u; asm("cvt.rna.tf32.f32 %0, %1;" : "=r"(u) : "f"(f));
    return __uint_as_float(u);
}
#define MMA_TF32(C, a0,a1,a2,a3, b0,b1)                                        \
    asm volatile("mma.sync.aligned.m16n8k8.row.col.f32.tf32.tf32.f32 "         \
                 "{%0,%1,%2,%3}, {%4,%5,%6,%7}, {%8,%9}, {%0,%1,%2,%3};"       \
                 : "+f"((C)[0]), "+f"((C)[1]), "+f"((C)[2]), "+f"((C)[3])      \
                 : "r"(a0), "r"(a1), "r"(a2), "r"(a3), "r"(b0), "r"(b1))

__device__ __forceinline__ int ld_acq(const int* p) {
    int v; asm volatile("ld.acquire.gpu.global.s32 %0, [%1];" : "=r"(v) : "l"(p) : "memory");
    return v;
}

// ---------------- weight packing ---------------------------------------------
__global__ void pack_weights(const float* __restrict__ Wg,
                             const float* __restrict__ Wh,
                             const float* __restrict__ Wo) {
    int idx = blockIdx.x * blockDim.x + threadIdx.x;
    const int s1 = Hn * N1, s2 = Hn * 1024, s3 = Hn * Hn, s4 = Hn * On;
    if (idx < s1) {
        int k = idx / N1, n = idx % N1;
        g_WxT[idx] = (n < 1024) ? Wg[n * 1024 + k] : Wh[(n - 1024) * 1024 + k];
    } else if (idx < s1 + s2) {
        int r = idx - s1; int k = r / 1024, j = r % 1024;
        g_WgHt[r] = Wg[j * 1024 + 512 + k];
    } else if (idx < s1 + s2 + s3) {
        int r = idx - s1 - s2; int k = r / 512, j = r % 512;
        g_WhHt[r] = Wh[j * 1024 + 512 + k];
    } else if (idx < s1 + s2 + s3 + s4) {
        int r = idx - s1 - s2 - s3; int k = r / 512, o = r % 512;
        g_WoT[r] = Wo[o * 512 + k];
    }
}

// ---------------- tf32 MMA GEMM: C[M,N] = A[M,K] @ Bt[K,N] (+bias) -----------
// 64x64 tile, BK=16, 256 thr = 8 warps (4 row x 2 col), warp tile 16x32.
__global__ void gemm_tf32(const float* __restrict__ A, const float* __restrict__ Bt,
                          float* __restrict__ C, const float* __restrict__ bias,
                          int M, int N, int K) {
    __shared__ float As[16][68];
    __shared__ float Bs[16][68];
    int tid = threadIdx.x, w = tid >> 5, l = tid & 31;
    int wm = w >> 1, wn = w & 1;
    int mBase = blockIdx.y * 64, nBase = blockIdx.x * 64;
    float acc[4][4] = {};
    for (int k0 = 0; k0 < K; k0 += 16) {
        {
            int m = tid >> 2, kq = (tid & 3) * 4;
            int gm = mBase + m;
            float4 v = make_float4(0.f, 0.f, 0.f, 0.f);
            if (gm < M) v = *(const float4*)&A[(size_t)gm * K + k0 + kq];
            As[kq + 0][m] = f2tff(v.x); As[kq + 1][m] = f2tff(v.y);
            As[kq + 2][m] = f2tff(v.z); As[kq + 3][m] = f2tff(v.w);
        }
        {
            int kk = tid >> 4, n = (tid & 15) * 4;
            float4 v = *(const float4*)&Bt[(size_t)(k0 + kk) * N + nBase + n];
            Bs[kk][n + 0] = f2tff(v.x); Bs[kk][n + 1] = f2tff(v.y);
            Bs[kk][n + 2] = f2tff(v.z); Bs[kk][n + 3] = f2tff(v.w);
        }
        __syncthreads();
        #pragma unroll
        for (int ks = 0; ks < 2; ks++) {
            int ar = wm * 16 + (l >> 2);
            int ac = ks * 8 + (l & 3);
            uint32_t a0 = __float_as_uint(As[ac][ar]);
            uint32_t a1 = __float_as_uint(As[ac][ar + 8]);
            uint32_t a2 = __float_as_uint(As[ac + 4][ar]);
            uint32_t a3 = __float_as_uint(As[ac + 4][ar + 8]);
            #pragma unroll
            for (int nt = 0; nt < 4; nt++) {
                int n = wn * 32 + nt * 8 + (l >> 2);
                uint32_t b0 = __float_as_uint(Bs[ks * 8 + (l & 3)][n]);
                uint32_t b1 = __float_as_uint(Bs[ks * 8 + 4 + (l & 3)][n]);
                MMA_TF32(acc[nt], a0, a1, a2, a3, b0, b1);
            }
        }
        __syncthreads();
    }
    #pragma unroll
    for (int nt = 0; nt < 4; nt++) {
        #pragma unroll
        for (int rr = 0; rr < 4; rr++) {
            int row = mBase + wm * 16 + (l >> 2) + ((rr >= 2) ? 8 : 0);
            if (row >= M) continue;
            int col = nBase + wn * 32 + nt * 8 + (l & 3) * 2 + (rr & 1);
            float v = acc[nt][rr];
            if (bias) v += bias[col];
            C[(size_t)row * N + col] = v;
        }
    }
}

// ---------------- persistent GRU recurrence ----------------------------------
__global__ void __launch_bounds__(256, 1)
gru_persistent(const int* __restrict__ x, const float* __restrict__ bg,
               const float* __restrict__ bh) {
    extern __shared__ float sm[];
    float* sWg = sm;                          // [512][PAD_WG], 64 cols used
    float* sWh = sWg + 512 * PAD_WG;          // [512][PAD_WH], 32 cols used
    float* sSt = sWh + 512 * PAD_WH;          // [32][PAD_ST], 128 cols used

    const int jt  = blockIdx.x & 15;
    const int g   = blockIdx.x >> 4;
    const int tid = threadIdx.x;
    const int w   = tid >> 5, l = tid & 31;
    const int mt  = w & 1;                    // 16-row half
    const int wn  = w >> 1;                   // 0..3
    const int bBase = g * RB;

    // cache tf32-rounded weight slices (reused 256 steps)
    for (int i = tid; i < 512 * 64; i += 256) {
        int k = i >> 6, c = i & 63;
        sWg[k * PAD_WG + c] = f2tff(g_WgHt[k * 1024 + jt * 64 + c]);
    }
    for (int i = tid; i < 512 * 32; i += 256) {
        int k = i >> 5, c = i & 31;
        sWh[k * PAD_WH + c] = f2tff(g_WhHt[k * 512 + jt * 32 + c]);
    }
    __syncthreads();

    const int row0 = bBase + mt * 16 + (l >> 2);
    float bgv[4], bhv[2];
    #pragma unroll
    for (int ti = 0; ti < 2; ti++)
        #pragma unroll
        for (int p = 0; p < 2; p++)
            bgv[ti * 2 + p] = bg[jt * 64 + wn * 16 + ti * 8 + (l & 3) * 2 + p];
    #pragma unroll
    for (int p = 0; p < 2; p++)
        bhv[p] = bh[jt * 32 + wn * 8 + (l & 3) * 2 + p];

    int target = 0;
    for (int t = 0; t < Sn; t++) {
        const int tok0 = __ldg(&x[row0 * Sn + t]);
        const int tok1 = __ldg(&x[(row0 + 8) * Sn + t]);

        // ========== phase 1: gates ==========
        float acc[8] = {};
        for (int pass = 0; pass < 4; pass++) {
            const int kb = pass * 128;
            for (int i = tid; i < 1024; i += 256) {
                int row = i >> 5, kq = (i & 31) * 4;
                float4 v = __ldcg((const float4*)&g_h[(bBase + row) * 512 + kb + kq]);
                sSt[row * PAD_ST + kq + 0] = f2tff(v.x);
                sSt[row * PAD_ST + kq + 1] = f2tff(v.y);
                sSt[row * PAD_ST + kq + 2] = f2tff(v.z);
                sSt[row * PAD_ST + kq + 3] = f2tff(v.w);
            }
            __syncthreads();
            #pragma unroll
            for (int ks = 0; ks < 16; ks++) {
                const float* ap = &sSt[(mt * 16 + (l >> 2)) * PAD_ST + ks * 8 + (l & 3)];
                uint32_t a0 = __float_as_uint(ap[0]);
                uint32_t a1 = __float_as_uint(ap[8 * PAD_ST]);
                uint32_t a2 = __float_as_uint(ap[4]);
                uint32_t a3 = __float_as_uint(ap[8 * PAD_ST + 4]);
                const int kg = kb + ks * 8 + (l & 3);
                #pragma unroll
                for (int ti = 0; ti < 2; ti++) {
                    int n = wn * 16 + ti * 8 + (l >> 2);
                    uint32_t b0 = __float_as_uint(sWg[kg * PAD_WG + n]);
                    uint32_t b1 = __float_as_uint(sWg[(kg + 4) * PAD_WG + n]);
                    MMA_TF32(acc + ti * 4, a0, a1, a2, a3, b0, b1);
                }
            }
            __syncthreads();
        }
        #pragma unroll
        for (int ti = 0; ti < 2; ti++) {
            #pragma unroll
            for (int rr = 0; rr < 4; rr++) {
                int row = (rr < 2) ? row0 : (row0 + 8);
                int tok = (rr < 2) ? tok0 : tok1;
                int colL = jt * 64 + wn * 16 + ti * 8 + (l & 3) * 2 + (rr & 1);
                float gv = acc[ti * 4 + rr]
                         + __ldg(&g_EmbW[(size_t)tok * N1 + colL]) + bgv[ti * 2 + (rr & 1)];
                float s = 1.f / (1.f + __expf(-gv));
                if (jt < 8) {
                    __stcg(&g_z[row * 512 + colL], s);
                } else {
                    int c = colL - 512;
                    __stcg(&g_rh[row * 512 + c], s * __ldcg(&g_h[row * 512 + c]));
                }
            }
        }
        // ---- group barrier 1 ----
        target += NJ;
        __syncthreads();
        if (tid == 0) {
            __threadfence();
            atomicAdd(&g_ctr[g], 1);
            while (ld_acq(&g_ctr[g]) < target) {}
            __threadfence();
        }
        __syncthreads();

        // ========== phase 2: candidate + update ==========
        float acc2[4] = {};
        for (int pass = 0; pass < 4; pass++) {
            const int kb = pass * 128;
            for (int i = tid; i < 1024; i += 256) {
                int row = i >> 5, kq = (i & 31) * 4;
                float4 v = __ldcg((const float4*)&g_rh[(bBase + row) * 512 + kb + kq]);
                sSt[row * PAD_ST + kq + 0] = f2tff(v.x);
                sSt[row * PAD_ST + kq + 1] = f2tff(v.y);
                sSt[row * PAD_ST + kq + 2] = f2tff(v.z);
                sSt[row * PAD_ST + kq + 3] = f2tff(v.w);
            }
            __syncthreads();
            #pragma unroll
            for (int ks = 0; ks < 16; ks++) {
                const float* ap = &sSt[(mt * 16 + (l >> 2)) * PAD_ST + ks * 8 + (l & 3)];
                uint32_t a0 = __float_as_uint(ap[0]);
                uint32_t a1 = __float_as_uint(ap[8 * PAD_ST]);
                uint32_t a2 = __float_as_uint(ap[4]);
                uint32_t a3 = __float_as_uint(ap[8 * PAD_ST + 4]);
                const int kg = kb + ks * 8 + (l & 3);
                int n = wn * 8 + (l >> 2);
                uint32_t b0 = __float_as_uint(sWh[kg * PAD_WH + n]);
                uint32_t b1 = __float_as_uint(sWh[(kg + 4) * PAD_WH + n]);
                MMA_TF32(acc2, a0, a1, a2, a3, b0, b1);
            }
            __syncthreads();
        }
        #pragma unroll
        for (int rr = 0; rr < 4; rr++) {
            int row = (rr < 2) ? row0 : (row0 + 8);
            int tok = (rr < 2) ? tok0 : tok1;
            int col = jt * 32 + wn * 8 + (l & 3) * 2 + (rr & 1);
            float cand = tanhf(acc2[rr] + __ldg(&g_EmbW[(size_t)tok * N1 + 1024 + col])
                               + bhv[rr & 1]);
            float zz = __ldcg(&g_z[row * 512 + col]);
            float hp = __ldcg(&g_h[row * 512 + col]);
            float hn = fmaf(zz, cand - hp, hp);
            __stcg(&g_h[row * 512 + col], hn);
            __stcg(&g_Hs[((size_t)row * Sn + t) * 512 + col], hn);
        }
        // ---- group barrier 2 ----
        target += NJ;
        __syncthreads();
        if (tid == 0) {
            __threadfence();
            atomicAdd(&g_ctr[g], 1);
            while (ld_acq(&g_ctr[g]) < target) {}
            __threadfence();
        }
        __syncthreads();
    }
}

// ---------------- tiny helpers ----------------------------------------------
__global__ void zero_misc() {
    int i = blockIdx.x * blockDim.x + threadIdx.x;
    if (i < Bn * Hn) g_h[i] = 0.f;
    if (i < NG) g_ctr[i] = 0;
}
__global__ void copy_h(float* __restrict__ out) {
    int i = blockIdx.x * blockDim.x + threadIdx.x;
    if (i < Bn * Hn) out[i] = g_h[i];
}

// ---------------- entry ------------------------------------------------------
extern "C" void kernel_launch(void* const* d_in, const int* in_sizes, int n_in,
                              void* d_out, int out_size) {
    const int*   x   = (const int*)  d_in[0];
    const float* emb = (const float*)d_in[1];
    const float* Wg  = (const float*)d_in[2];
    const float* bg  = (const float*)d_in[3];
    const float* Wh  = (const float*)d_in[4];
    const float* bh  = (const float*)d_in[5];
    const float* Wo  = (const float*)d_in[6];
    const float* bo  = (const float*)d_in[7];
    float* out = (float*)d_out;

    float *pEmbW, *pWxT, *pWoT, *pHs;
    cudaGetSymbolAddress((void**)&pEmbW, g_EmbW);
    cudaGetSymbolAddress((void**)&pWxT,  g_WxT);
    cudaGetSymbolAddress((void**)&pWoT,  g_WoT);
    cudaGetSymbolAddress((void**)&pHs,   g_Hs);

    cudaFuncSetAttribute(gru_persistent,
                         cudaFuncAttributeMaxDynamicSharedMemorySize, SMEM_BYTES);

    pack_weights<<<7168, 256>>>(Wg, Wh, Wo);
    gemm_tf32<<<dim3(N1 / 64, (Vn + 63) / 64), 256>>>(emb, pWxT, pEmbW, nullptr,
                                                      Vn, N1, Hn);
    zero_misc<<<(Bn * Hn + 255) / 256, 256>>>();
    gru_persistent<<<128, 256, SMEM_BYTES>>>(x, bg, bh);
    gemm_tf32<<<dim3(On / 64, (Bn * Sn) / 64), 256>>>(pHs, pWoT, out + Bn * Hn, bo,
                                                      Bn * Sn, On, Hn);
    copy_h<<<(Bn * Hn + 255) / 256, 256>>>(out);
}

// round 4
// speedup vs baseline: 5.3819x; 2.2576x over previous
#include <cuda_runtime.h>
#include <math.h>
#include <stdint.h>

#define Vn 10000
#define Hn 512
#define On 512
#define Bn 256
#define Sn 256
#define N1 1536

#define NJ 16
#define NG 8
#define RB 32
#define PAD_ST 132
// swizzled weight tiles: no padding
#define SMEM_BYTES ((512*64 + 512*32 + 32*PAD_ST) * 4)

// ---------------- scratch ----------------------------------------------------
__device__ float g_EmbW[(size_t)Vn * N1];
__device__ float g_embR[(size_t)Vn * Hn];      // tf32-rounded emb
__device__ float g_WxT [Hn * N1];              // tf32-rounded
__device__ float g_WgHt[Hn * 1024];
__device__ float g_WhHt[Hn * Hn];
__device__ float g_WoT [Hn * On];              // tf32-rounded
__device__ float g_h   [Bn * Hn];
__device__ float g_z   [Bn * Hn];
__device__ float g_rh  [Bn * Hn];              // tf32-rounded
__device__ float g_Hs  [(size_t)Bn * Sn * Hn]; // tf32-rounded
__device__ int   g_ctr [NG];

// ---------------- helpers ----------------------------------------------------
__device__ __forceinline__ float f2tff(float f) {
    uint32_t u; asm("cvt.rna.tf32.f32 %0, %1;" : "=r"(u) : "f"(f));
    return __uint_as_float(u);
}
#define MMA_TF32(C, a0,a1,a2,a3, b0,b1)                                        \
    asm volatile("mma.sync.aligned.m16n8k8.row.col.f32.tf32.tf32.f32 "         \
                 "{%0,%1,%2,%3}, {%4,%5,%6,%7}, {%8,%9}, {%0,%1,%2,%3};"       \
                 : "+f"((C)[0]), "+f"((C)[1]), "+f"((C)[2]), "+f"((C)[3])      \
                 : "r"(a0), "r"(a1), "r"(a2), "r"(a3), "r"(b0), "r"(b1))

__device__ __forceinline__ int ld_acq(const int* p) {
    int v; asm volatile("ld.acquire.gpu.global.s32 %0, [%1];" : "=r"(v) : "l"(p) : "memory");
    return v;
}
__device__ __forceinline__ uint32_t s2u(const void* p) {
    return (uint32_t)__cvta_generic_to_shared(p);
}
__device__ __forceinline__ void cp16(uint32_t dst, const void* src, bool pred) {
    int sz = pred ? 16 : 0;
    asm volatile("cp.async.cg.shared.global [%0], [%1], 16, %2;"
                 :: "r"(dst), "l"(src), "r"(sz) : "memory");
}
#define CP_COMMIT() asm volatile("cp.async.commit_group;" ::: "memory")
#define CP_WAIT1()  asm volatile("cp.async.wait_group 1;" ::: "memory")

// ---------------- weight packing ---------------------------------------------
__global__ void pack_weights(const float* __restrict__ Wg,
                             const float* __restrict__ Wh,
                             const float* __restrict__ Wo) {
    int idx = blockIdx.x * blockDim.x + threadIdx.x;
    const int s1 = Hn * N1, s2 = Hn * 1024, s3 = Hn * Hn, s4 = Hn * On;
    if (idx < s1) {
        int k = idx / N1, n = idx % N1;
        g_WxT[idx] = f2tff((n < 1024) ? Wg[n * 1024 + k] : Wh[(n - 1024) * 1024 + k]);
    } else if (idx < s1 + s2) {
        int r = idx - s1; int k = r / 1024, j = r % 1024;
        g_WgHt[r] = Wg[j * 1024 + 512 + k];
    } else if (idx < s1 + s2 + s3) {
        int r = idx - s1 - s2; int k = r / 512, j = r % 512;
        g_WhHt[r] = Wh[j * 1024 + 512 + k];
    } else if (idx < s1 + s2 + s3 + s4) {
        int r = idx - s1 - s2 - s3; int k = r / 512, o = r % 512;
        g_WoT[r] = f2tff(Wo[o * 512 + k]);
    }
}

__global__ void round_emb(const float* __restrict__ emb) {
    int i = blockIdx.x * blockDim.x + threadIdx.x;
    if (i < Vn * Hn) g_embR[i] = f2tff(emb[i]);
}

// ------- double-buffered tf32 GEMM: C[M,N] = A[M,K] @ Bt[K,N] (+bias) -------
// BM=128, BN=64, BK=16, 256 thr = 8 warps (4m x 2n), warp tile 32x32.
// A,Bt must be pre-rounded to tf32 values. K=512, N % 64 == 0.
__global__ void __launch_bounds__(256)
gemm_db(const float* __restrict__ A, const float* __restrict__ Bt,
        float* __restrict__ C, const float* __restrict__ bias,
        int M, int N, int K) {
    __shared__ float As[2][128 * 20];
    __shared__ float Bs[2][16 * 72];
    const int tid = threadIdx.x, w = tid >> 5, l = tid & 31;
    const int wm = w >> 1, wn = w & 1;
    const int mBase = blockIdx.y * 128, nBase = blockIdx.x * 64;

    // staging geometry
    const int ar = tid >> 1, ac = (tid & 1) * 8;      // A: 2 thr/row, 2x16B each
    const int br = tid >> 4, bc = (tid & 15) * 4;     // B: 1x16B each

    auto stage = [&](int s, int k0) {
        bool pA = (mBase + ar) < M;
        const float* srcA = &A[(size_t)(mBase + ar) * K + k0 + ac];
        cp16(s2u(&As[s][ar * 20 + ac]),     srcA,     pA);
        cp16(s2u(&As[s][ar * 20 + ac + 4]), srcA + 4, pA);
        cp16(s2u(&Bs[s][br * 72 + bc]), &Bt[(size_t)(k0 + br) * N + nBase + bc], true);
    };

    float acc[2][4][4] = {};
    const int nIter = K / 16;
    stage(0, 0); CP_COMMIT();
    for (int it = 0; it < nIter; it++) {
        if (it + 1 < nIter) stage((it + 1) & 1, (it + 1) * 16);
        CP_COMMIT();
        CP_WAIT1();
        __syncthreads();
        const float* as = As[it & 1];
        const float* bs = Bs[it & 1];
        #pragma unroll
        for (int ks = 0; ks < 2; ks++) {
            const int kk = ks * 8 + (l & 3);
            uint32_t bfr[4][2];
            #pragma unroll
            for (int nt = 0; nt < 4; nt++) {
                int n = wn * 32 + nt * 8 + (l >> 2);
                bfr[nt][0] = __float_as_uint(bs[kk * 72 + n]);
                bfr[nt][1] = __float_as_uint(bs[(kk + 4) * 72 + n]);
            }
            #pragma unroll
            for (int mt = 0; mt < 2; mt++) {
                int r = wm * 32 + mt * 16 + (l >> 2);
                uint32_t a0 = __float_as_uint(as[r * 20 + kk]);
                uint32_t a1 = __float_as_uint(as[(r + 8) * 20 + kk]);
                uint32_t a2 = __float_as_uint(as[r * 20 + kk + 4]);
                uint32_t a3 = __float_as_uint(as[(r + 8) * 20 + kk + 4]);
                #pragma unroll
                for (int nt = 0; nt < 4; nt++)
                    MMA_TF32(acc[mt][nt], a0, a1, a2, a3, bfr[nt][0], bfr[nt][1]);
            }
        }
        __syncthreads();
    }
    #pragma unroll
    for (int mt = 0; mt < 2; mt++) {
        #pragma unroll
        for (int nt = 0; nt < 4; nt++) {
            #pragma unroll
            for (int rr = 0; rr < 4; rr++) {
                int row = mBase + wm * 32 + mt * 16 + (l >> 2) + ((rr >= 2) ? 8 : 0);
                if (row >= M) continue;
                int col = nBase + wn * 32 + nt * 8 + (l & 3) * 2 + (rr & 1);
                float v = acc[mt][nt][rr];
                if (bias) v += bias[col];
                C[(size_t)row * N + col] = v;
            }
        }
    }
}

// ---------------- persistent GRU recurrence ----------------------------------
__global__ void __launch_bounds__(256, 1)
gru_persistent(const int* __restrict__ x, const float* __restrict__ bg,
               const float* __restrict__ bh) {
    extern __shared__ float sm[];
    float* sWg = sm;                          // [512][64] swizzled
    float* sWh = sWg + 512 * 64;              // [512][32] swizzled
    float* sSt = sWh + 512 * 32;              // [32][PAD_ST]

    const int jt  = blockIdx.x & 15;
    const int g   = blockIdx.x >> 4;
    const int tid = threadIdx.x;
    const int w   = tid >> 5, l = tid & 31;
    const int mt  = w & 1;
    const int wn  = w >> 1;
    const int bBase = g * RB;

    // cache tf32-rounded weight slices, XOR-swizzled (bank-conflict-free frags)
    for (int i = tid; i < 512 * 64; i += 256) {
        int k = i >> 6, c = i & 63;
        sWg[k * 64 + (c ^ ((k & 3) * 8))] = f2tff(g_WgHt[k * 1024 + jt * 64 + c]);
    }
    for (int i = tid; i < 512 * 32; i += 256) {
        int k = i >> 5, c = i & 31;
        sWh[k * 32 + (c ^ ((k & 3) * 8))] = f2tff(g_WhHt[k * 512 + jt * 32 + c]);
    }
    __syncthreads();

    const int row0 = bBase + mt * 16 + (l >> 2);
    float bgv[4], bhv[2];
    #pragma unroll
    for (int ti = 0; ti < 2; ti++)
        #pragma unroll
        for (int p = 0; p < 2; p++)
            bgv[ti * 2 + p] = bg[jt * 64 + wn * 16 + ti * 8 + (l & 3) * 2 + p];
    #pragma unroll
    for (int p = 0; p < 2; p++)
        bhv[p] = bh[jt * 32 + wn * 8 + (l & 3) * 2 + p];

    int target = 0;
    for (int t = 0; t < Sn; t++) {
        const int tok0 = __ldg(&x[row0 * Sn + t]);
        const int tok1 = __ldg(&x[(row0 + 8) * Sn + t]);

        // ---- prefetch all epilogue operands (hidden under MMA loops) ----
        float ew1[8], hv1[8];
        #pragma unroll
        for (int ti = 0; ti < 2; ti++)
            #pragma unroll
            for (int rr = 0; rr < 4; rr++) {
                int tok = (rr < 2) ? tok0 : tok1;
                int colL = jt * 64 + wn * 16 + ti * 8 + (l & 3) * 2 + (rr & 1);
                ew1[ti * 4 + rr] = __ldg(&g_EmbW[(size_t)tok * N1 + colL]);
            }
        if (jt >= 8) {
            #pragma unroll
            for (int ti = 0; ti < 2; ti++)
                #pragma unroll
                for (int rr = 0; rr < 4; rr++) {
                    int row = (rr < 2) ? row0 : (row0 + 8);
                    int c = jt * 64 + wn * 16 + ti * 8 + (l & 3) * 2 + (rr & 1) - 512;
                    hv1[ti * 4 + rr] = __ldcg(&g_h[row * 512 + c]);
                }
        }
        float ew2[4], hp2[4];
        #pragma unroll
        for (int rr = 0; rr < 4; rr++) {
            int tok = (rr < 2) ? tok0 : tok1;
            int row = (rr < 2) ? row0 : (row0 + 8);
            int col2 = jt * 32 + wn * 8 + (l & 3) * 2 + (rr & 1);
            ew2[rr] = __ldg(&g_EmbW[(size_t)tok * N1 + 1024 + col2]);
            hp2[rr] = __ldcg(&g_h[row * 512 + col2]);
        }

        // ========== phase 1: gates ==========
        float acc[8] = {};
        {
            float4 pf[4];
            #pragma unroll
            for (int j = 0; j < 4; j++) {
                int i = tid + j * 256; int row = i >> 5, kq = (i & 31) * 4;
                pf[j] = __ldcg((const float4*)&g_h[(bBase + row) * 512 + kq]);
            }
            for (int pass = 0; pass < 4; pass++) {
                const int kb = pass * 128;
                #pragma unroll
                for (int j = 0; j < 4; j++) {
                    int i = tid + j * 256; int row = i >> 5, kq = (i & 31) * 4;
                    sSt[row * PAD_ST + kq + 0] = f2tff(pf[j].x);
                    sSt[row * PAD_ST + kq + 1] = f2tff(pf[j].y);
                    sSt[row * PAD_ST + kq + 2] = f2tff(pf[j].z);
                    sSt[row * PAD_ST + kq + 3] = f2tff(pf[j].w);
                }
                if (pass < 3) {
                    #pragma unroll
                    for (int j = 0; j < 4; j++) {
                        int i = tid + j * 256; int row = i >> 5, kq = (i & 31) * 4;
                        pf[j] = __ldcg((const float4*)&g_h[(bBase + row) * 512 + kb + 128 + kq]);
                    }
                }
                __syncthreads();
                #pragma unroll
                for (int ks = 0; ks < 16; ks++) {
                    const float* ap = &sSt[(mt * 16 + (l >> 2)) * PAD_ST + ks * 8 + (l & 3)];
                    uint32_t a0 = __float_as_uint(ap[0]);
                    uint32_t a1 = __float_as_uint(ap[8 * PAD_ST]);
                    uint32_t a2 = __float_as_uint(ap[4]);
                    uint32_t a3 = __float_as_uint(ap[8 * PAD_ST + 4]);
                    const int kg = kb + ks * 8 + (l & 3);
                    const int sw = (kg & 3) * 8;
                    #pragma unroll
                    for (int ti = 0; ti < 2; ti++) {
                        int n = (wn * 16 + ti * 8 + (l >> 2)) ^ sw;
                        uint32_t b0 = __float_as_uint(sWg[kg * 64 + n]);
                        uint32_t b1 = __float_as_uint(sWg[(kg + 4) * 64 + n]);
                        MMA_TF32(acc + ti * 4, a0, a1, a2, a3, b0, b1);
                    }
                }
                __syncthreads();
            }
        }
        #pragma unroll
        for (int ti = 0; ti < 2; ti++) {
            #pragma unroll
            for (int rr = 0; rr < 4; rr++) {
                int row = (rr < 2) ? row0 : (row0 + 8);
                int colL = jt * 64 + wn * 16 + ti * 8 + (l & 3) * 2 + (rr & 1);
                float gv = acc[ti * 4 + rr] + ew1[ti * 4 + rr] + bgv[ti * 2 + (rr & 1)];
                float s = 1.f / (1.f + __expf(-gv));
                if (jt < 8) {
                    __stcg(&g_z[row * 512 + colL], s);
                } else {
                    __stcg(&g_rh[row * 512 + colL - 512], f2tff(s * hv1[ti * 4 + rr]));
                }
            }
        }
        // ---- group barrier 1 ----
        target += NJ;
        __syncthreads();
        if (tid == 0) {
            __threadfence();
            atomicAdd(&g_ctr[g], 1);
            while (ld_acq(&g_ctr[g]) < target) {}
            __threadfence();
        }
        __syncthreads();

        // prefetch z (written in phase1 by peer CTAs)
        float zz[4];
        #pragma unroll
        for (int rr = 0; rr < 4; rr++) {
            int row = (rr < 2) ? row0 : (row0 + 8);
            int col2 = jt * 32 + wn * 8 + (l & 3) * 2 + (rr & 1);
            zz[rr] = __ldcg(&g_z[row * 512 + col2]);
        }

        // ========== phase 2: candidate + update ==========
        float acc2[4] = {};
        {
            float4 pf[4];
            #pragma unroll
            for (int j = 0; j < 4; j++) {
                int i = tid + j * 256; int row = i >> 5, kq = (i & 31) * 4;
                pf[j] = __ldcg((const float4*)&g_rh[(bBase + row) * 512 + kq]);
            }
            for (int pass = 0; pass < 4; pass++) {
                const int kb = pass * 128;
                #pragma unroll
                for (int j = 0; j < 4; j++) {
                    int i = tid + j * 256; int row = i >> 5, kq = (i & 31) * 4;
                    *(float4*)&sSt[row * PAD_ST + kq] = pf[j];   // pre-rounded
                }
                if (pass < 3) {
                    #pragma unroll
                    for (int j = 0; j < 4; j++) {
                        int i = tid + j * 256; int row = i >> 5, kq = (i & 31) * 4;
                        pf[j] = __ldcg((const float4*)&g_rh[(bBase + row) * 512 + kb + 128 + kq]);
                    }
                }
                __syncthreads();
                #pragma unroll
                for (int ks = 0; ks < 16; ks++) {
                    const float* ap = &sSt[(mt * 16 + (l >> 2)) * PAD_ST + ks * 8 + (l & 3)];
                    uint32_t a0 = __float_as_uint(ap[0]);
                    uint32_t a1 = __float_as_uint(ap[8 * PAD_ST]);
                    uint32_t a2 = __float_as_uint(ap[4]);
                    uint32_t a3 = __float_as_uint(ap[8 * PAD_ST + 4]);
                    const int kg = kb + ks * 8 + (l & 3);
                    const int sw = (kg & 3) * 8;
                    int n = (wn * 8 + (l >> 2)) ^ sw;
                    uint32_t b0 = __float_as_uint(sWh[kg * 32 + n]);
                    uint32_t b1 = __float_as_uint(sWh[(kg + 4) * 32 + n]);
                    MMA_TF32(acc2, a0, a1, a2, a3, b0, b1);
                }
                __syncthreads();
            }
        }
        #pragma unroll
        for (int rr = 0; rr < 4; rr++) {
            int row = (rr < 2) ? row0 : (row0 + 8);
            int col2 = jt * 32 + wn * 8 + (l & 3) * 2 + (rr & 1);
            float cand = tanhf(acc2[rr] + ew2[rr] + bhv[rr & 1]);
            float hn = fmaf(zz[rr], cand - hp2[rr], hp2[rr]);
            __stcg(&g_h[row * 512 + col2], hn);
            __stcg(&g_Hs[((size_t)row * Sn + t) * 512 + col2], f2tff(hn));
        }
        // ---- group barrier 2 ----
        target += NJ;
        __syncthreads();
        if (tid == 0) {
            __threadfence();
            atomicAdd(&g_ctr[g], 1);
            while (ld_acq(&g_ctr[g]) < target) {}
            __threadfence();
        }
        __syncthreads();
    }
}

// ---------------- tiny helpers ----------------------------------------------
__global__ void zero_misc() {
    int i = blockIdx.x * blockDim.x + threadIdx.x;
    if (i < Bn * Hn) g_h[i] = 0.f;
    if (i < NG) g_ctr[i] = 0;
}
__global__ void copy_h(float* __restrict__ out) {
    int i = blockIdx.x * blockDim.x + threadIdx.x;
    if (i < Bn * Hn) out[i] = g_h[i];
}

// ---------------- entry ------------------------------------------------------
extern "C" void kernel_launch(void* const* d_in, const int* in_sizes, int n_in,
                              void* d_out, int out_size) {
    const int*   x   = (const int*)  d_in[0];
    const float* emb = (const float*)d_in[1];
    const float* Wg  = (const float*)d_in[2];
    const float* bg  = (const float*)d_in[3];
    const float* Wh  = (const float*)d_in[4];
    const float* bh  = (const float*)d_in[5];
    const float* Wo  = (const float*)d_in[6];
    const float* bo  = (const float*)d_in[7];
    float* out = (float*)d_out;

    float *pEmbW, *pEmbR, *pWxT, *pWoT, *pHs;
    cudaGetSymbolAddress((void**)&pEmbW, g_EmbW);
    cudaGetSymbolAddress((void**)&pEmbR, g_embR);
    cudaGetSymbolAddress((void**)&pWxT,  g_WxT);
    cudaGetSymbolAddress((void**)&pWoT,  g_WoT);
    cudaGetSymbolAddress((void**)&pHs,   g_Hs);

    cudaFuncSetAttribute(gru_persistent,
                         cudaFuncAttributeMaxDynamicSharedMemorySize, SMEM_BYTES);

    pack_weights<<<7168, 256>>>(Wg, Wh, Wo);
    round_emb<<<(Vn * Hn + 255) / 256, 256>>>(emb);
    gemm_db<<<dim3(N1 / 64, (Vn + 127) / 128), 256>>>(pEmbR, pWxT, pEmbW, nullptr,
                                                      Vn, N1, Hn);
    zero_misc<<<(Bn * Hn + 255) / 256, 256>>>();
    gru_persistent<<<128, 256, SMEM_BYTES>>>(x, bg, bh);
    gemm_db<<<dim3(On / 64, (Bn * Sn) / 128), 256>>>(pHs, pWoT, out + Bn * Hn, bo,
                                                     Bn * Sn, On, Hn);
    copy_h<<<(Bn * Hn + 255) / 256, 256>>>(out);
}

// round 5
// speedup vs baseline: 5.4904x; 1.0202x over previous
#include <cuda_runtime.h>
#include <math.h>
#include <stdint.h>

#define Vn 10000
#define Hn 512
#define On 512
#define Bn 256
#define Sn 256
#define N1 1536

#define NJ 16
#define NG 8
#define RB 32
#define PAD_ST 132
#define SMEM_BYTES ((512*64 + 512*32 + 2*32*PAD_ST) * 4)

// ---------------- scratch ----------------------------------------------------
__device__ float g_EmbW[(size_t)Vn * N1];
__device__ float g_embR[(size_t)Vn * Hn];      // tf32-rounded emb
__device__ float g_WxT [Hn * N1];              // tf32-rounded
__device__ float g_WgHt[Hn * 1024];
__device__ float g_WhHt[Hn * Hn];
__device__ float g_WoT [Hn * On];              // tf32-rounded
__device__ float g_h   [Bn * Hn];
__device__ float g_z   [Bn * Hn];
__device__ float g_rh  [Bn * Hn];              // tf32-rounded
__device__ float g_Hs  [(size_t)Bn * Sn * Hn]; // tf32-rounded
__device__ int   g_ctr [NG];

// ---------------- helpers ----------------------------------------------------
__device__ __forceinline__ float f2tff(float f) {
    uint32_t u; asm("cvt.rna.tf32.f32 %0, %1;" : "=r"(u) : "f"(f));
    return __uint_as_float(u);
}
#define MMA_TF32(C, a0,a1,a2,a3, b0,b1)                                        \
    asm volatile("mma.sync.aligned.m16n8k8.row.col.f32.tf32.tf32.f32 "         \
                 "{%0,%1,%2,%3}, {%4,%5,%6,%7}, {%8,%9}, {%0,%1,%2,%3};"       \
                 : "+f"((C)[0]), "+f"((C)[1]), "+f"((C)[2]), "+f"((C)[3])      \
                 : "r"(a0), "r"(a1), "r"(a2), "r"(a3), "r"(b0), "r"(b1))

__device__ __forceinline__ int ld_acq(const int* p) {
    int v; asm volatile("ld.acquire.gpu.global.s32 %0, [%1];" : "=r"(v) : "l"(p) : "memory");
    return v;
}
__device__ __forceinline__ uint32_t s2u(const void* p) {
    return (uint32_t)__cvta_generic_to_shared(p);
}
__device__ __forceinline__ void cp16(uint32_t dst, const void* src, bool pred) {
    int sz = pred ? 16 : 0;
    asm volatile("cp.async.cg.shared.global [%0], [%1], 16, %2;"
                 :: "r"(dst), "l"(src), "r"(sz) : "memory");
}
#define CP_COMMIT() asm volatile("cp.async.commit_group;" ::: "memory")
#define CP_WAIT1()  asm volatile("cp.async.wait_group 1;" ::: "memory")

// ---------------- weight packing ---------------------------------------------
__global__ void pack_weights(const float* __restrict__ Wg,
                             const float* __restrict__ Wh,
                             const float* __restrict__ Wo) {
    int idx = blockIdx.x * blockDim.x + threadIdx.x;
    const int s1 = Hn * N1, s2 = Hn * 1024, s3 = Hn * Hn, s4 = Hn * On;
    if (idx < s1) {
        int k = idx / N1, n = idx % N1;
        g_WxT[idx] = f2tff((n < 1024) ? Wg[n * 1024 + k] : Wh[(n - 1024) * 1024 + k]);
    } else if (idx < s1 + s2) {
        int r = idx - s1; int k = r / 1024, j = r % 1024;
        g_WgHt[r] = Wg[j * 1024 + 512 + k];
    } else if (idx < s1 + s2 + s3) {
        int r = idx - s1 - s2; int k = r / 512, j = r % 512;
        g_WhHt[r] = Wh[j * 1024 + 512 + k];
    } else if (idx < s1 + s2 + s3 + s4) {
        int r = idx - s1 - s2 - s3; int k = r / 512, o = r % 512;
        g_WoT[r] = f2tff(Wo[o * 512 + k]);
    }
}

__global__ void round_emb(const float* __restrict__ emb) {
    int i = blockIdx.x * blockDim.x + threadIdx.x;
    if (i < Vn * Hn) g_embR[i] = f2tff(emb[i]);
}

// ------- double-buffered tf32 GEMM: C[M,N] = A[M,K] @ Bt[K,N] (+bias) -------
// BM=128, BN=128, BK=16, 256 thr = 8 warps (2m x 4n), warp tile 64x32.
// A,Bt pre-rounded to tf32 values. K % 16 == 0, N % 128 == 0.
__global__ void __launch_bounds__(256)
gemm_db(const float* __restrict__ A, const float* __restrict__ Bt,
        float* __restrict__ C, const float* __restrict__ bias,
        int M, int N, int K) {
    __shared__ float As[2][128 * 20];
    __shared__ float Bs[2][16 * 136];
    const int tid = threadIdx.x, w = tid >> 5, l = tid & 31;
    const int wm = w >> 2, wn = w & 3;
    const int mBase = blockIdx.y * 128, nBase = blockIdx.x * 128;

    const int ar = tid >> 1, ac = (tid & 1) * 8;      // A: 2 thr/row
    const int br = tid >> 4, bc = (tid & 15) * 4;     // B: 16 thr/row, 2x16B

    auto stage = [&](int s, int k0) {
        bool pA = (mBase + ar) < M;
        const float* srcA = &A[(size_t)(mBase + ar) * K + k0 + ac];
        cp16(s2u(&As[s][ar * 20 + ac]),     srcA,     pA);
        cp16(s2u(&As[s][ar * 20 + ac + 4]), srcA + 4, pA);
        const float* srcB = &Bt[(size_t)(k0 + br) * N + nBase + bc];
        cp16(s2u(&Bs[s][br * 136 + bc]),      srcB,      true);
        cp16(s2u(&Bs[s][br * 136 + bc + 64]), srcB + 64, true);
    };

    float acc[4][4][4] = {};   // [mt][nt][frag]
    const int nIter = K / 16;
    stage(0, 0); CP_COMMIT();
    for (int it = 0; it < nIter; it++) {
        if (it + 1 < nIter) stage((it + 1) & 1, (it + 1) * 16);
        CP_COMMIT();
        CP_WAIT1();
        __syncthreads();
        const float* as = As[it & 1];
        const float* bs = Bs[it & 1];
        #pragma unroll
        for (int ks = 0; ks < 2; ks++) {
            const int kk = ks * 8 + (l & 3);
            uint32_t bfr[4][2];
            #pragma unroll
            for (int nt = 0; nt < 4; nt++) {
                int n = wn * 32 + nt * 8 + (l >> 2);
                bfr[nt][0] = __float_as_uint(bs[kk * 136 + n]);
                bfr[nt][1] = __float_as_uint(bs[(kk + 4) * 136 + n]);
            }
            #pragma unroll
            for (int mt = 0; mt < 4; mt++) {
                int r = wm * 64 + mt * 16 + (l >> 2);
                uint32_t a0 = __float_as_uint(as[r * 20 + kk]);
                uint32_t a1 = __float_as_uint(as[(r + 8) * 20 + kk]);
                uint32_t a2 = __float_as_uint(as[r * 20 + kk + 4]);
                uint32_t a3 = __float_as_uint(as[(r + 8) * 20 + kk + 4]);
                #pragma unroll
                for (int nt = 0; nt < 4; nt++)
                    MMA_TF32(acc[mt][nt], a0, a1, a2, a3, bfr[nt][0], bfr[nt][1]);
            }
        }
        __syncthreads();
    }
    #pragma unroll
    for (int mt = 0; mt < 4; mt++) {
        #pragma unroll
        for (int nt = 0; nt < 4; nt++) {
            #pragma unroll
            for (int rr = 0; rr < 4; rr++) {
                int row = mBase + wm * 64 + mt * 16 + (l >> 2) + ((rr >= 2) ? 8 : 0);
                if (row >= M) continue;
                int col = nBase + wn * 32 + nt * 8 + (l & 3) * 2 + (rr & 1);
                float v = acc[mt][nt][rr];
                if (bias) v += bias[col];
                C[(size_t)row * N + col] = v;
            }
        }
    }
}

// ---------------- persistent GRU recurrence ----------------------------------
__global__ void __launch_bounds__(256, 1)
gru_persistent(const int* __restrict__ x, const float* __restrict__ bg,
               const float* __restrict__ bh) {
    extern __shared__ float sm[];
    float* sWg  = sm;                          // [512][64] swizzled
    float* sWh  = sWg + 512 * 64;              // [512][32] swizzled
    float* sSt0 = sWh + 512 * 32;              // [32][PAD_ST] buffer 0
    float* sSt1 = sSt0 + 32 * PAD_ST;          // [32][PAD_ST] buffer 1

    const int jt  = blockIdx.x & 15;
    const int g   = blockIdx.x >> 4;
    const int tid = threadIdx.x;
    const int w   = tid >> 5, l = tid & 31;
    const int mt  = w & 1;
    const int wn  = w >> 1;
    const int bBase = g * RB;

    // cache tf32-rounded weight slices, XOR-swizzled
    for (int i = tid; i < 512 * 64; i += 256) {
        int k = i >> 6, c = i & 63;
        sWg[k * 64 + (c ^ ((k & 3) * 8))] = f2tff(g_WgHt[k * 1024 + jt * 64 + c]);
    }
    for (int i = tid; i < 512 * 32; i += 256) {
        int k = i >> 5, c = i & 31;
        sWh[k * 32 + (c ^ ((k & 3) * 8))] = f2tff(g_WhHt[k * 512 + jt * 32 + c]);
    }
    __syncthreads();

    const int row0 = bBase + mt * 16 + (l >> 2);
    float bgv[4], bhv[2];
    #pragma unroll
    for (int ti = 0; ti < 2; ti++)
        #pragma unroll
        for (int p = 0; p < 2; p++)
            bgv[ti * 2 + p] = bg[jt * 64 + wn * 16 + ti * 8 + (l & 3) * 2 + p];
    #pragma unroll
    for (int p = 0; p < 2; p++)
        bhv[p] = bh[jt * 32 + wn * 8 + (l & 3) * 2 + p];

    // per-thread staging indices
    int srow[4], skq[4];
    #pragma unroll
    for (int j = 0; j < 4; j++) {
        int i = tid + j * 256;
        srow[j] = i >> 5; skq[j] = (i & 31) * 4;
    }

    int target = 0;
    for (int t = 0; t < Sn; t++) {
        const int tok0 = __ldg(&x[row0 * Sn + t]);
        const int tok1 = __ldg(&x[(row0 + 8) * Sn + t]);

        // ---- prefetch epilogue operands ----
        float ew1[8], hv1[8];
        #pragma unroll
        for (int ti = 0; ti < 2; ti++)
            #pragma unroll
            for (int rr = 0; rr < 4; rr++) {
                int tok = (rr < 2) ? tok0 : tok1;
                int colL = jt * 64 + wn * 16 + ti * 8 + (l & 3) * 2 + (rr & 1);
                ew1[ti * 4 + rr] = __ldg(&g_EmbW[(size_t)tok * N1 + colL]);
            }
        if (jt >= 8) {
            #pragma unroll
            for (int ti = 0; ti < 2; ti++)
                #pragma unroll
                for (int rr = 0; rr < 4; rr++) {
                    int row = (rr < 2) ? row0 : (row0 + 8);
                    int c = jt * 64 + wn * 16 + ti * 8 + (l & 3) * 2 + (rr & 1) - 512;
                    hv1[ti * 4 + rr] = __ldcg(&g_h[row * 512 + c]);
                }
        }
        float ew2[4], hp2[4];
        #pragma unroll
        for (int rr = 0; rr < 4; rr++) {
            int tok = (rr < 2) ? tok0 : tok1;
            int row = (rr < 2) ? row0 : (row0 + 8);
            int col2 = jt * 32 + wn * 8 + (l & 3) * 2 + (rr & 1);
            ew2[rr] = __ldg(&g_EmbW[(size_t)tok * N1 + 1024 + col2]);
            hp2[rr] = __ldcg(&g_h[row * 512 + col2]);
        }

        // ========== phase 1: gates (double-buffered staging) ==========
        float acc[8] = {};
        {
            float4 pf[4];
            #pragma unroll
            for (int j = 0; j < 4; j++)
                pf[j] = __ldcg((const float4*)&g_h[(bBase + srow[j]) * 512 + skq[j]]);
            #pragma unroll
            for (int j = 0; j < 4; j++) {
                float4 o = make_float4(f2tff(pf[j].x), f2tff(pf[j].y),
                                       f2tff(pf[j].z), f2tff(pf[j].w));
                *(float4*)&sSt0[srow[j] * PAD_ST + skq[j]] = o;
            }
            for (int pass = 0; pass < 4; pass++) {
                const int kb = pass * 128;
                if (pass < 3) {
                    #pragma unroll
                    for (int j = 0; j < 4; j++)
                        pf[j] = __ldcg((const float4*)&g_h[(bBase + srow[j]) * 512
                                                           + kb + 128 + skq[j]]);
                }
                __syncthreads();
                const float* st = (pass & 1) ? sSt1 : sSt0;
                #pragma unroll
                for (int ks = 0; ks < 16; ks++) {
                    const float* ap = &st[(mt * 16 + (l >> 2)) * PAD_ST + ks * 8 + (l & 3)];
                    uint32_t a0 = __float_as_uint(ap[0]);
                    uint32_t a1 = __float_as_uint(ap[8 * PAD_ST]);
                    uint32_t a2 = __float_as_uint(ap[4]);
                    uint32_t a3 = __float_as_uint(ap[8 * PAD_ST + 4]);
                    const int kg = kb + ks * 8 + (l & 3);
                    const int sw = (kg & 3) * 8;
                    #pragma unroll
                    for (int ti = 0; ti < 2; ti++) {
                        int n = (wn * 16 + ti * 8 + (l >> 2)) ^ sw;
                        uint32_t b0 = __float_as_uint(sWg[kg * 64 + n]);
                        uint32_t b1 = __float_as_uint(sWg[(kg + 4) * 64 + n]);
                        MMA_TF32(acc + ti * 4, a0, a1, a2, a3, b0, b1);
                    }
                }
                if (pass < 3) {
                    float* dst = (pass & 1) ? sSt0 : sSt1;
                    #pragma unroll
                    for (int j = 0; j < 4; j++) {
                        float4 o = make_float4(f2tff(pf[j].x), f2tff(pf[j].y),
                                               f2tff(pf[j].z), f2tff(pf[j].w));
                        *(float4*)&dst[srow[j] * PAD_ST + skq[j]] = o;
                    }
                }
            }
        }
        #pragma unroll
        for (int ti = 0; ti < 2; ti++) {
            #pragma unroll
            for (int rr = 0; rr < 4; rr++) {
                int row = (rr < 2) ? row0 : (row0 + 8);
                int colL = jt * 64 + wn * 16 + ti * 8 + (l & 3) * 2 + (rr & 1);
                float gv = acc[ti * 4 + rr] + ew1[ti * 4 + rr] + bgv[ti * 2 + (rr & 1)];
                float s = 1.f / (1.f + __expf(-gv));
                if (jt < 8) {
                    __stcg(&g_z[row * 512 + colL], s);
                } else {
                    __stcg(&g_rh[row * 512 + colL - 512], f2tff(s * hv1[ti * 4 + rr]));
                }
            }
        }
        // ---- group barrier 1 ----
        target += NJ;
        __syncthreads();
        if (tid == 0) {
            __threadfence();
            atomicAdd(&g_ctr[g], 1);
            while (ld_acq(&g_ctr[g]) < target) {}
            __threadfence();
        }
        __syncthreads();

        float zz[4];
        #pragma unroll
        for (int rr = 0; rr < 4; rr++) {
            int row = (rr < 2) ? row0 : (row0 + 8);
            int col2 = jt * 32 + wn * 8 + (l & 3) * 2 + (rr & 1);
            zz[rr] = __ldcg(&g_z[row * 512 + col2]);
        }

        // ========== phase 2: candidate + update (double-buffered) ==========
        float acc2[4] = {};
        {
            float4 pf[4];
            #pragma unroll
            for (int j = 0; j < 4; j++)
                pf[j] = __ldcg((const float4*)&g_rh[(bBase + srow[j]) * 512 + skq[j]]);
            #pragma unroll
            for (int j = 0; j < 4; j++)
                *(float4*)&sSt0[srow[j] * PAD_ST + skq[j]] = pf[j];  // pre-rounded
            for (int pass = 0; pass < 4; pass++) {
                const int kb = pass * 128;
                if (pass < 3) {
                    #pragma unroll
                    for (int j = 0; j < 4; j++)
                        pf[j] = __ldcg((const float4*)&g_rh[(bBase + srow[j]) * 512
                                                            + kb + 128 + skq[j]]);
                }
                __syncthreads();
                const float* st = (pass & 1) ? sSt1 : sSt0;
                #pragma unroll
                for (int ks = 0; ks < 16; ks++) {
                    const float* ap = &st[(mt * 16 + (l >> 2)) * PAD_ST + ks * 8 + (l & 3)];
                    uint32_t a0 = __float_as_uint(ap[0]);
                    uint32_t a1 = __float_as_uint(ap[8 * PAD_ST]);
                    uint32_t a2 = __float_as_uint(ap[4]);
                    uint32_t a3 = __float_as_uint(ap[8 * PAD_ST + 4]);
                    const int kg = kb + ks * 8 + (l & 3);
                    const int sw = (kg & 3) * 8;
                    int n = (wn * 8 + (l >> 2)) ^ sw;
                    uint32_t b0 = __float_as_uint(sWh[kg * 32 + n]);
                    uint32_t b1 = __float_as_uint(sWh[(kg + 4) * 32 + n]);
                    MMA_TF32(acc2, a0, a1, a2, a3, b0, b1);
                }
                if (pass < 3) {
                    float* dst = (pass & 1) ? sSt0 : sSt1;
                    #pragma unroll
                    for (int j = 0; j < 4; j++)
                        *(float4*)&dst[srow[j] * PAD_ST + skq[j]] = pf[j];
                }
            }
        }
        #pragma unroll
        for (int rr = 0; rr < 4; rr++) {
            int row = (rr < 2) ? row0 : (row0 + 8);
            int col2 = jt * 32 + wn * 8 + (l & 3) * 2 + (rr & 1);
            float cand = tanhf(acc2[rr] + ew2[rr] + bhv[rr & 1]);
            float hn = fmaf(zz[rr], cand - hp2[rr], hp2[rr]);
            __stcg(&g_h[row * 512 + col2], hn);
            __stcg(&g_Hs[((size_t)row * Sn + t) * 512 + col2], f2tff(hn));
        }
        // ---- group barrier 2 ----
        target += NJ;
        __syncthreads();
        if (tid == 0) {
            __threadfence();
            atomicAdd(&g_ctr[g], 1);
            while (ld_acq(&g_ctr[g]) < target) {}
            __threadfence();
        }
        __syncthreads();
    }
}

// ---------------- tiny helpers ----------------------------------------------
__global__ void zero_misc() {
    int i = blockIdx.x * blockDim.x + threadIdx.x;
    if (i < Bn * Hn) g_h[i] = 0.f;
    if (i < NG) g_ctr[i] = 0;
}
__global__ void copy_h(float* __restrict__ out) {
    int i = blockIdx.x * blockDim.x + threadIdx.x;
    if (i < Bn * Hn) out[i] = g_h[i];
}

// ---------------- entry ------------------------------------------------------
extern "C" void kernel_launch(void* const* d_in, const int* in_sizes, int n_in,
                              void* d_out, int out_size) {
    const int*   x   = (const int*)  d_in[0];
    const float* emb = (const float*)d_in[1];
    const float* Wg  = (const float*)d_in[2];
    const float* bg  = (const float*)d_in[3];
    const float* Wh  = (const float*)d_in[4];
    const float* bh  = (const float*)d_in[5];
    const float* Wo  = (const float*)d_in[6];
    const float* bo  = (const float*)d_in[7];
    float* out = (float*)d_out;

    float *pEmbW, *pEmbR, *pWxT, *pWoT, *pHs;
    cudaGetSymbolAddress((void**)&pEmbW, g_EmbW);
    cudaGetSymbolAddress((void**)&pEmbR, g_embR);
    cudaGetSymbolAddress((void**)&pWxT,  g_WxT);
    cudaGetSymbolAddress((void**)&pWoT,  g_WoT);
    cudaGetSymbolAddress((void**)&pHs,   g_Hs);

    cudaFuncSetAttribute(gru_persistent,
                         cudaFuncAttributeMaxDynamicSharedMemorySize, SMEM_BYTES);

    pack_weights<<<7168, 256>>>(Wg, Wh, Wo);
    round_emb<<<(Vn * Hn + 255) / 256, 256>>>(emb);
    gemm_db<<<dim3(N1 / 128, (Vn + 127) / 128), 256>>>(pEmbR, pWxT, pEmbW, nullptr,
                                                       Vn, N1, Hn);
    zero_misc<<<(Bn * Hn + 255) / 256, 256>>>();
    gru_persistent<<<128, 256, SMEM_BYTES>>>(x, bg, bh);
    gemm_db<<<dim3(On / 128, (Bn * Sn) / 128), 256>>>(pHs, pWoT, out + Bn * Hn, bo,
                                                      Bn * Sn, On, Hn);
    copy_h<<<(Bn * Hn + 255) / 256, 256>>>(out);
}